// round 3
// baseline (speedup 1.0000x reference)
#include <cuda_runtime.h>
#include <cuda_bf16.h>
#include <math.h>

// Problem constants
#define BB 4
#define SS 2048
#define DD 1024
#define HH 8
#define EE 128
#define HE (HH * EE)   // 1024

#define NEG_BIG (-3.402823466e38f)

// ---------------- scratch (device globals; no allocs) ----------------
__device__ float g_qh[(size_t)BB * HH * SS * EE];  // [b,h,s,e] 32MB
__device__ float g_kh[(size_t)BB * HH * SS * EE];
__device__ float g_vh[(size_t)BB * HH * SS * EE];
__device__ float g_z [(size_t)BB * SS * HE];       // [b,s,h*E+e] 32MB

// ---------------- helpers ----------------
__device__ __forceinline__ unsigned f2tf(float x) {
    unsigned u;
    asm("cvt.rna.tf32.f32 %0, %1;" : "=r"(u) : "f"(x));
    return u;
}

__device__ __forceinline__ void mma_tf32(float& d0, float& d1, float& d2, float& d3,
                                         unsigned a0, unsigned a1, unsigned a2, unsigned a3,
                                         unsigned b0, unsigned b1)
{
    asm volatile(
        "mma.sync.aligned.m16n8k8.row.col.f32.tf32.tf32.f32 "
        "{%0,%1,%2,%3}, {%4,%5,%6,%7}, {%8,%9}, {%0,%1,%2,%3};\n"
        : "+f"(d0), "+f"(d1), "+f"(d2), "+f"(d3)
        : "r"(a0), "r"(a1), "r"(a2), "r"(a3), "r"(b0), "r"(b1));
}

// =====================================================================
// Fused projection GEMM (tensor cores, tf32, reg-prefetch pipeline):
//   which = z/32 selects (q,Wq,qh,scale) / (k,Wk,kh) / (v,Wv,vh)
//   per (b,h): C[S x 128] = X[b][S x 1024] * W[h][1024 x 128] * scale
// Block: 128x128 tile, KC=32, 256 threads (8 warps, warp tile 32x64).
// grid = (1, S/128, 3*B*H)
// =====================================================================
#define ASTR 36
#define BSTR 136

__global__ __launch_bounds__(256, 2) void proj_tc(
    const float* __restrict__ Xq, const float* __restrict__ Xk, const float* __restrict__ Xv,
    const float* __restrict__ Wq, const float* __restrict__ Wk, const float* __restrict__ Wv,
    float* __restrict__ Oq, float* __restrict__ Ok, float* __restrict__ Ov,
    float qscale)
{
    __shared__ unsigned As[128 * ASTR];
    __shared__ unsigned Bs[32 * BSTR];

    int zz = blockIdx.z;
    int which = zz >> 5;        // 0=q 1=k 2=v
    int bh = zz & 31;
    int b = bh >> 3, h = bh & 7;

    const float* X = (which == 0) ? Xq : (which == 1) ? Xk : Xv;
    const float* W = (which == 0) ? Wq : (which == 1) ? Wk : Wv;
    float* Out     = (which == 0) ? Oq : (which == 1) ? Ok : Ov;
    float scale    = (which == 0) ? qscale : 1.0f;

    const float* A  = X + (size_t)b * SS * DD;
    const float* Bw = W + (size_t)h * DD * EE;
    float* C = Out + (size_t)bh * SS * EE;
    int s0 = blockIdx.y * 128;

    int tid = threadIdx.x;
    int warp = tid >> 5, lane = tid & 31;
    int g = lane >> 2, c = lane & 3;
    int wm = warp >> 1, wn = warp & 1;

    float acc[2][8][4];
#pragma unroll
    for (int i = 0; i < 2; i++)
#pragma unroll
        for (int j = 0; j < 8; j++)
#pragma unroll
            for (int t = 0; t < 4; t++) acc[i][j][t] = 0.f;

    // prefetch regs
    float4 pa[4], pb[4];
#pragma unroll
    for (int it = 0; it < 4; it++) {
        int idx = tid + it * 256;
        int r = idx >> 3, c4 = (idx & 7) * 4;
        pa[it] = *(const float4*)(A + (size_t)(s0 + r) * DD + c4);
        int r2 = idx >> 5, c42 = (idx & 31) * 4;
        pb[it] = *(const float4*)(Bw + (size_t)r2 * EE + c42);
    }

    for (int k0 = 0; k0 < DD; k0 += 32) {
        // store prefetched tile (cvt tf32, STS.128)
#pragma unroll
        for (int it = 0; it < 4; it++) {
            int idx = tid + it * 256;
            int r = idx >> 3, c4 = (idx & 7) * 4;
            uint4 ua;
            ua.x = f2tf(pa[it].x); ua.y = f2tf(pa[it].y);
            ua.z = f2tf(pa[it].z); ua.w = f2tf(pa[it].w);
            *(uint4*)(&As[r * ASTR + c4]) = ua;
            int r2 = idx >> 5, c42 = (idx & 31) * 4;
            uint4 ub;
            ub.x = f2tf(pb[it].x); ub.y = f2tf(pb[it].y);
            ub.z = f2tf(pb[it].z); ub.w = f2tf(pb[it].w);
            *(uint4*)(&Bs[r2 * BSTR + c42]) = ub;
        }
        __syncthreads();

        // prefetch next tile (overlaps compute)
        if (k0 + 32 < DD) {
#pragma unroll
            for (int it = 0; it < 4; it++) {
                int idx = tid + it * 256;
                int r = idx >> 3, c4 = (idx & 7) * 4;
                pa[it] = *(const float4*)(A + (size_t)(s0 + r) * DD + k0 + 32 + c4);
                int r2 = idx >> 5, c42 = (idx & 31) * 4;
                pb[it] = *(const float4*)(Bw + (size_t)(k0 + 32 + r2) * EE + c42);
            }
        }

#pragma unroll
        for (int kk = 0; kk < 32; kk += 8) {
            unsigned a[2][4];
#pragma unroll
            for (int mi = 0; mi < 2; mi++) {
                int base = (wm * 32 + mi * 16 + g) * ASTR + kk + c;
                a[mi][0] = As[base];
                a[mi][1] = As[base + 8 * ASTR];
                a[mi][2] = As[base + 4];
                a[mi][3] = As[base + 8 * ASTR + 4];
            }
            unsigned bf[8][2];
#pragma unroll
            for (int jt = 0; jt < 8; jt++) {
                int base = (kk + c) * BSTR + wn * 64 + jt * 8 + g;
                bf[jt][0] = Bs[base];
                bf[jt][1] = Bs[base + 4 * BSTR];
            }
#pragma unroll
            for (int mi = 0; mi < 2; mi++)
#pragma unroll
                for (int jt = 0; jt < 8; jt++)
                    mma_tf32(acc[mi][jt][0], acc[mi][jt][1], acc[mi][jt][2], acc[mi][jt][3],
                             a[mi][0], a[mi][1], a[mi][2], a[mi][3],
                             bf[jt][0], bf[jt][1]);
        }
        __syncthreads();
    }

#pragma unroll
    for (int mi = 0; mi < 2; mi++) {
        int r = s0 + wm * 32 + mi * 16 + g;
#pragma unroll
        for (int jt = 0; jt < 8; jt++) {
            int col = wn * 64 + jt * 8 + 2 * c;
            *(float2*)(C + (size_t)r * EE + col) =
                make_float2(acc[mi][jt][0] * scale, acc[mi][jt][1] * scale);
            *(float2*)(C + (size_t)(r + 8) * EE + col) =
                make_float2(acc[mi][jt][2] * scale, acc[mi][jt][3] * scale);
        }
    }
}

// =====================================================================
// Output GEMM (tensor cores, reg-prefetch): Out = Z*Wo + bo
// grid = (D/128, B*S/128)
// =====================================================================
__global__ __launch_bounds__(256, 2) void out_tc(
    const float* __restrict__ Z, const float* __restrict__ Wo,
    const float* __restrict__ bo, float* __restrict__ Out)
{
    __shared__ unsigned As[128 * ASTR];
    __shared__ unsigned Bs[32 * BSTR];

    int row0 = blockIdx.y * 128;
    int col0 = blockIdx.x * 128;

    int tid = threadIdx.x;
    int warp = tid >> 5, lane = tid & 31;
    int g = lane >> 2, c = lane & 3;
    int wm = warp >> 1, wn = warp & 1;

    float acc[2][8][4];
#pragma unroll
    for (int i = 0; i < 2; i++)
#pragma unroll
        for (int j = 0; j < 8; j++)
#pragma unroll
            for (int t = 0; t < 4; t++) acc[i][j][t] = 0.f;

    float4 pa[4], pb[4];
#pragma unroll
    for (int it = 0; it < 4; it++) {
        int idx = tid + it * 256;
        int r = idx >> 3, c4 = (idx & 7) * 4;
        pa[it] = *(const float4*)(Z + (size_t)(row0 + r) * HE + c4);
        int r2 = idx >> 5, c42 = (idx & 31) * 4;
        pb[it] = *(const float4*)(Wo + (size_t)r2 * DD + col0 + c42);
    }

    for (int k0 = 0; k0 < HE; k0 += 32) {
#pragma unroll
        for (int it = 0; it < 4; it++) {
            int idx = tid + it * 256;
            int r = idx >> 3, c4 = (idx & 7) * 4;
            uint4 ua;
            ua.x = f2tf(pa[it].x); ua.y = f2tf(pa[it].y);
            ua.z = f2tf(pa[it].z); ua.w = f2tf(pa[it].w);
            *(uint4*)(&As[r * ASTR + c4]) = ua;
            int r2 = idx >> 5, c42 = (idx & 31) * 4;
            uint4 ub;
            ub.x = f2tf(pb[it].x); ub.y = f2tf(pb[it].y);
            ub.z = f2tf(pb[it].z); ub.w = f2tf(pb[it].w);
            *(uint4*)(&Bs[r2 * BSTR + c42]) = ub;
        }
        __syncthreads();

        if (k0 + 32 < HE) {
#pragma unroll
            for (int it = 0; it < 4; it++) {
                int idx = tid + it * 256;
                int r = idx >> 3, c4 = (idx & 7) * 4;
                pa[it] = *(const float4*)(Z + (size_t)(row0 + r) * HE + k0 + 32 + c4);
                int r2 = idx >> 5, c42 = (idx & 31) * 4;
                pb[it] = *(const float4*)(Wo + (size_t)(k0 + 32 + r2) * DD + col0 + c42);
            }
        }

#pragma unroll
        for (int kk = 0; kk < 32; kk += 8) {
            unsigned a[2][4];
#pragma unroll
            for (int mi = 0; mi < 2; mi++) {
                int base = (wm * 32 + mi * 16 + g) * ASTR + kk + c;
                a[mi][0] = As[base];
                a[mi][1] = As[base + 8 * ASTR];
                a[mi][2] = As[base + 4];
                a[mi][3] = As[base + 8 * ASTR + 4];
            }
            unsigned bf[8][2];
#pragma unroll
            for (int jt = 0; jt < 8; jt++) {
                int base = (kk + c) * BSTR + wn * 64 + jt * 8 + g;
                bf[jt][0] = Bs[base];
                bf[jt][1] = Bs[base + 4 * BSTR];
            }
#pragma unroll
            for (int mi = 0; mi < 2; mi++)
#pragma unroll
                for (int jt = 0; jt < 8; jt++)
                    mma_tf32(acc[mi][jt][0], acc[mi][jt][1], acc[mi][jt][2], acc[mi][jt][3],
                             a[mi][0], a[mi][1], a[mi][2], a[mi][3],
                             bf[jt][0], bf[jt][1]);
        }
        __syncthreads();
    }

#pragma unroll
    for (int mi = 0; mi < 2; mi++) {
        int r = row0 + wm * 32 + mi * 16 + g;
#pragma unroll
        for (int jt = 0; jt < 8; jt++) {
            int col = col0 + wn * 64 + jt * 8 + 2 * c;
            float b0 = bo[col], b1 = bo[col + 1];
            *(float2*)(Out + (size_t)r * DD + col) =
                make_float2(acc[mi][jt][0] + b0, acc[mi][jt][1] + b1);
            *(float2*)(Out + (size_t)(r + 8) * DD + col) =
                make_float2(acc[mi][jt][2] + b0, acc[mi][jt][3] + b1);
        }
    }
}

// =====================================================================
// Flash attention v3 (tf32 MMA), per (b,h).
// FBM=128 q rows, FBN=128 keys/tile, 512 threads (16 warps, 4x4 warp grid,
// warp tile 32x32 in both phases). K and V share one smem buffer; next
// tile register-prefetched during compute. grid = (S/128, B*H).
// =====================================================================
#define FBM 128
#define FBN 128
#define FSTR 132
#define NT (SS / FBN)   // 16 key tiles

extern "C" __global__ __launch_bounds__(512, 1) void flash_tc(
    const float* __restrict__ qh, const float* __restrict__ kh,
    const float* __restrict__ vh, float* __restrict__ z)
{
    extern __shared__ unsigned sm[];
    unsigned* Qs  = sm;                       // 128*132 tf32
    unsigned* KVs = Qs + FBM * FSTR;          // 128*132 tf32 (K, then V, alternating)
    float*    Sf  = (float*)(KVs + FBN * FSTR); // 128*132 scores fp32 / P tf32
    unsigned* Su  = (unsigned*)Sf;
    float* mrow = Sf + FBM * FSTR;            // 128
    float* lrow = mrow + FBM;
    float* arow = lrow + FBM;

    int bh = blockIdx.y;
    int b = bh >> 3, h = bh & 7;
    int q0 = blockIdx.x * FBM;

    const float* Qg = qh + ((size_t)bh * SS + q0) * EE;
    const float* Kg = kh + (size_t)bh * SS * EE;
    const float* Vg = vh + (size_t)bh * SS * EE;

    int tid = threadIdx.x;
    int warp = tid >> 5, lane = tid & 31;
    int g = lane >> 2, c = lane & 3;
    int wm = warp >> 2, wn = warp & 3;   // 4x4 warp grid

    // ---- stage Q (tf32) ----
#pragma unroll
    for (int it = 0; it < 8; it++) {
        int idx = tid + it * 512;
        int r = idx >> 5, c4 = (idx & 31) * 4;
        float4 v = *(const float4*)(Qg + (size_t)r * EE + c4);
        uint4 u;
        u.x = f2tf(v.x); u.y = f2tf(v.y); u.z = f2tf(v.z); u.w = f2tf(v.w);
        *(uint4*)(&Qs[r * FSTR + c4]) = u;
    }
    if (tid < FBM) { mrow[tid] = NEG_BIG; lrow[tid] = 0.f; }

    // ---- prologue: K(0) -> smem, V(0) -> regs ----
    float4 rv[8];
#pragma unroll
    for (int i = 0; i < 8; i++)
        rv[i] = *(const float4*)(Kg + (size_t)(tid + i * 512) * 4);
#pragma unroll
    for (int i = 0; i < 8; i++) {
        int flat = tid + i * 512;
        int r = flat >> 5, c4 = (flat & 31) * 4;
        uint4 u;
        u.x = f2tf(rv[i].x); u.y = f2tf(rv[i].y);
        u.z = f2tf(rv[i].z); u.w = f2tf(rv[i].w);
        *(uint4*)(&KVs[r * FSTR + c4]) = u;
    }
#pragma unroll
    for (int i = 0; i < 8; i++)
        rv[i] = *(const float4*)(Vg + (size_t)(tid + i * 512) * 4);
    __syncthreads();

    float o[2][4][4];
#pragma unroll
    for (int i = 0; i < 2; i++)
#pragma unroll
        for (int j = 0; j < 4; j++)
#pragma unroll
            for (int t = 0; t < 4; t++) o[i][j][t] = 0.f;

    int srow = tid >> 2;      // softmax row
    int part = tid & 3;       // interleaved column group

    for (int kt = 0; kt < NT; kt++) {
        // ================= QK^T: S[128x128] = Q * K^T =================
        float sc[2][4][4];
#pragma unroll
        for (int i = 0; i < 2; i++)
#pragma unroll
            for (int j = 0; j < 4; j++)
#pragma unroll
                for (int t = 0; t < 4; t++) sc[i][j][t] = 0.f;

#pragma unroll
        for (int kk = 0; kk < EE; kk += 8) {
            unsigned a[2][4];
#pragma unroll
            for (int mi = 0; mi < 2; mi++) {
                int base = (wm * 32 + mi * 16 + g) * FSTR + kk + c;
                a[mi][0] = Qs[base];
                a[mi][1] = Qs[base + 8 * FSTR];
                a[mi][2] = Qs[base + 4];
                a[mi][3] = Qs[base + 8 * FSTR + 4];
            }
            unsigned bf[4][2];
#pragma unroll
            for (int jt = 0; jt < 4; jt++) {
                int base = (wn * 32 + jt * 8 + g) * FSTR + kk + c;
                bf[jt][0] = KVs[base];
                bf[jt][1] = KVs[base + 4];
            }
#pragma unroll
            for (int mi = 0; mi < 2; mi++)
#pragma unroll
                for (int jt = 0; jt < 4; jt++)
                    mma_tf32(sc[mi][jt][0], sc[mi][jt][1], sc[mi][jt][2], sc[mi][jt][3],
                             a[mi][0], a[mi][1], a[mi][2], a[mi][3],
                             bf[jt][0], bf[jt][1]);
        }
#pragma unroll
        for (int mi = 0; mi < 2; mi++) {
            int r = wm * 32 + mi * 16 + g;
#pragma unroll
            for (int jt = 0; jt < 4; jt++) {
                int col = wn * 32 + jt * 8 + 2 * c;
                *(float2*)(Sf + r * FSTR + col)       = make_float2(sc[mi][jt][0], sc[mi][jt][1]);
                *(float2*)(Sf + (r + 8) * FSTR + col) = make_float2(sc[mi][jt][2], sc[mi][jt][3]);
            }
        }
        __syncthreads();   // scores visible; QK done reading KVs (=K)

        // ========== store V(t) from regs; online softmax ==========
#pragma unroll
        for (int i = 0; i < 8; i++) {
            int flat = tid + i * 512;
            int r = flat >> 5, c4 = (flat & 31) * 4;
            uint4 u;
            u.x = f2tf(rv[i].x); u.y = f2tf(rv[i].y);
            u.z = f2tf(rv[i].z); u.w = f2tf(rv[i].w);
            *(uint4*)(&KVs[r * FSTR + c4]) = u;
        }
        {
            float* row = Sf + srow * FSTR;
            float vmax = NEG_BIG;
#pragma unroll
            for (int j = 0; j < 32; j++)
                vmax = fmaxf(vmax, row[part + 4 * j]);
            vmax = fmaxf(vmax, __shfl_xor_sync(0xffffffffu, vmax, 1));
            vmax = fmaxf(vmax, __shfl_xor_sync(0xffffffffu, vmax, 2));
            float m_old = mrow[srow];
            float m_new = fmaxf(m_old, vmax);
            float sum = 0.f;
            unsigned* rowu = Su + srow * FSTR;
#pragma unroll
            for (int j = 0; j < 32; j++) {
                float p = __expf(row[part + 4 * j] - m_new);
                sum += p;
                rowu[part + 4 * j] = f2tf(p);
            }
            sum += __shfl_xor_sync(0xffffffffu, sum, 1);
            sum += __shfl_xor_sync(0xffffffffu, sum, 2);
            if (part == 0) {
                float al = expf(m_old - m_new);
                arow[srow] = al;
                mrow[srow] = m_new;
                lrow[srow] = lrow[srow] * al + sum;
            }
        }
        __syncthreads();   // V + P + stats visible

        // ========== prefetch K(t+1); rescale O; PV ==========
        if (kt + 1 < NT) {
            const float* src = Kg + (size_t)(kt + 1) * FBN * EE;
#pragma unroll
            for (int i = 0; i < 8; i++)
                rv[i] = *(const float4*)(src + (size_t)(tid + i * 512) * 4);
        }
        {
            float a0 = arow[wm * 32 + g];
            float a1 = arow[wm * 32 + 8 + g];
            float a2 = arow[wm * 32 + 16 + g];
            float a3 = arow[wm * 32 + 24 + g];
#pragma unroll
            for (int jt = 0; jt < 4; jt++) {
                o[0][jt][0] *= a0; o[0][jt][1] *= a0;
                o[0][jt][2] *= a1; o[0][jt][3] *= a1;
                o[1][jt][0] *= a2; o[1][jt][1] *= a2;
                o[1][jt][2] *= a3; o[1][jt][3] *= a3;
            }
        }
#pragma unroll
        for (int kk = 0; kk < FBN; kk += 8) {
            unsigned a[2][4];
#pragma unroll
            for (int mi = 0; mi < 2; mi++) {
                int base = (wm * 32 + mi * 16 + g) * FSTR + kk + c;
                a[mi][0] = Su[base];
                a[mi][1] = Su[base + 8 * FSTR];
                a[mi][2] = Su[base + 4];
                a[mi][3] = Su[base + 8 * FSTR + 4];
            }
            unsigned bf[4][2];
#pragma unroll
            for (int jt = 0; jt < 4; jt++) {
                int base = (kk + c) * FSTR + wn * 32 + jt * 8 + g;
                bf[jt][0] = KVs[base];
                bf[jt][1] = KVs[base + 4 * FSTR];
            }
#pragma unroll
            for (int mi = 0; mi < 2; mi++)
#pragma unroll
                for (int jt = 0; jt < 4; jt++)
                    mma_tf32(o[mi][jt][0], o[mi][jt][1], o[mi][jt][2], o[mi][jt][3],
                             a[mi][0], a[mi][1], a[mi][2], a[mi][3],
                             bf[jt][0], bf[jt][1]);
        }
        __syncthreads();   // PV done reading KVs (=V)

        // ========== store K(t+1); prefetch V(t+1) ==========
        if (kt + 1 < NT) {
#pragma unroll
            for (int i = 0; i < 8; i++) {
                int flat = tid + i * 512;
                int r = flat >> 5, c4 = (flat & 31) * 4;
                uint4 u;
                u.x = f2tf(rv[i].x); u.y = f2tf(rv[i].y);
                u.z = f2tf(rv[i].z); u.w = f2tf(rv[i].w);
                *(uint4*)(&KVs[r * FSTR + c4]) = u;
            }
            const float* src = Vg + (size_t)(kt + 1) * FBN * EE;
#pragma unroll
            for (int i = 0; i < 8; i++)
                rv[i] = *(const float4*)(src + (size_t)(tid + i * 512) * 4);
            __syncthreads();   // K(t+1) visible
        }
    }

    // ---- finalize: divide by l, write to z[b, s, h*E + e] ----
    {
        float li0 = 1.f / lrow[wm * 32 + g];
        float li1 = 1.f / lrow[wm * 32 + 8 + g];
        float li2 = 1.f / lrow[wm * 32 + 16 + g];
        float li3 = 1.f / lrow[wm * 32 + 24 + g];
#pragma unroll
        for (int mi = 0; mi < 2; mi++) {
            int r = wm * 32 + mi * 16 + g;
            float lia = (mi == 0) ? li0 : li2;
            float lib = (mi == 0) ? li1 : li3;
            float* z0 = z + ((size_t)(b * SS + q0 + r)) * HE + h * EE;
            float* z1 = z + ((size_t)(b * SS + q0 + r + 8)) * HE + h * EE;
#pragma unroll
            for (int jt = 0; jt < 4; jt++) {
                int col = wn * 32 + jt * 8 + 2 * c;
                *(float2*)(z0 + col) = make_float2(o[mi][jt][0] * lia, o[mi][jt][1] * lia);
                *(float2*)(z1 + col) = make_float2(o[mi][jt][2] * lib, o[mi][jt][3] * lib);
            }
        }
    }
}

// =====================================================================
// launch
// =====================================================================
extern "C" void kernel_launch(void* const* d_in, const int* in_sizes, int n_in,
                              void* d_out, int out_size)
{
    const float* q  = (const float*)d_in[0];
    const float* k  = (const float*)d_in[1];
    const float* v  = (const float*)d_in[2];
    const float* Wq = (const float*)d_in[3];
    const float* Wk = (const float*)d_in[4];
    const float* Wv = (const float*)d_in[5];
    const float* Wo = (const float*)d_in[6];
    const float* bo = (const float*)d_in[7];
    float* out = (float*)d_out;

    float* qh; cudaGetSymbolAddress((void**)&qh, g_qh);
    float* kh; cudaGetSymbolAddress((void**)&kh, g_kh);
    float* vh; cudaGetSymbolAddress((void**)&vh, g_vh);
    float* z;  cudaGetSymbolAddress((void**)&z,  g_z);

    const int flash_smem = (3 * FBM * FSTR + 3 * FBM) * (int)sizeof(float);
    cudaFuncSetAttribute(flash_tc,
                         cudaFuncAttributeMaxDynamicSharedMemorySize, flash_smem);

    float qscale = 1.0f / sqrtf((float)EE);

    dim3 pgrid(1, SS / 128, 3 * BB * HH);
    proj_tc<<<pgrid, 256>>>(q, k, v, Wq, Wk, Wv, qh, kh, vh, qscale);

    dim3 fgrid(SS / FBM, BB * HH);
    flash_tc<<<fgrid, 512, flash_smem>>>(qh, kh, vh, z);

    dim3 ogrid(DD / 128, (BB * SS) / 128);
    out_tc<<<ogrid, 256>>>(z, Wo, bo, out);
}

// round 4
// speedup vs baseline: 1.0288x; 1.0288x over previous
#include <cuda_runtime.h>
#include <cuda_bf16.h>
#include <math.h>

// Problem constants
#define BB 4
#define SS 2048
#define DD 1024
#define HH 8
#define EE 128
#define HE (HH * EE)   // 1024

#define NEG_BIG (-3.402823466e38f)

// ---------------- scratch (device globals; no allocs) ----------------
__device__ float g_qh[(size_t)BB * HH * SS * EE];  // [b,h,s,e] pre-rounded tf32
__device__ float g_kh[(size_t)BB * HH * SS * EE];
__device__ float g_vh[(size_t)BB * HH * SS * EE];
__device__ float g_z [(size_t)BB * SS * HE];       // [b,s,h*E+e] pre-rounded tf32
// pre-rounded copies of inputs
__device__ float g_qr[(size_t)BB * SS * DD];
__device__ float g_kr[(size_t)BB * SS * DD];
__device__ float g_vr[(size_t)BB * SS * DD];
__device__ float g_wq[(size_t)HH * DD * EE];
__device__ float g_wk[(size_t)HH * DD * EE];
__device__ float g_wv[(size_t)HH * DD * EE];
__device__ float g_wo[(size_t)HE * DD];

// ---------------- helpers ----------------
__device__ __forceinline__ unsigned f2tf(float x) {
    unsigned u;
    asm("cvt.rna.tf32.f32 %0, %1;" : "=r"(u) : "f"(x));
    return u;
}
__device__ __forceinline__ float ftf(float x) { return __uint_as_float(f2tf(x)); }

__device__ __forceinline__ void mma_tf32(float& d0, float& d1, float& d2, float& d3,
                                         unsigned a0, unsigned a1, unsigned a2, unsigned a3,
                                         unsigned b0, unsigned b1)
{
    asm volatile(
        "mma.sync.aligned.m16n8k8.row.col.f32.tf32.tf32.f32 "
        "{%0,%1,%2,%3}, {%4,%5,%6,%7}, {%8,%9}, {%0,%1,%2,%3};\n"
        : "+f"(d0), "+f"(d1), "+f"(d2), "+f"(d3)
        : "r"(a0), "r"(a1), "r"(a2), "r"(a3), "r"(b0), "r"(b1));
}

__device__ __forceinline__ void cp16(void* smem_dst, const void* gmem_src) {
    unsigned s = (unsigned)__cvta_generic_to_shared(smem_dst);
    asm volatile("cp.async.cg.shared.global [%0], [%1], 16;\n" :: "r"(s), "l"(gmem_src));
}
#define CP_COMMIT() asm volatile("cp.async.commit_group;\n" ::: "memory")
#define CP_WAIT1()  asm volatile("cp.async.wait_group 1;\n" ::: "memory")
#define CP_WAIT0()  asm volatile("cp.async.wait_group 0;\n" ::: "memory")

// =====================================================================
// Pre-round kernels: write tf32-rounded fp32 copies (enables raw cp.async)
// =====================================================================
__global__ __launch_bounds__(256) void preround3(
    const float4* __restrict__ a, const float4* __restrict__ b, const float4* __restrict__ c,
    float4* __restrict__ A, float4* __restrict__ B, float4* __restrict__ C)
{
    size_t i = (size_t)blockIdx.x * 256 + threadIdx.x;
    const float4* src = (blockIdx.y == 0) ? a : (blockIdx.y == 1) ? b : c;
    float4* dst       = (blockIdx.y == 0) ? A : (blockIdx.y == 1) ? B : C;
    float4 v = src[i];
    v.x = ftf(v.x); v.y = ftf(v.y); v.z = ftf(v.z); v.w = ftf(v.w);
    dst[i] = v;
}
__global__ __launch_bounds__(256) void preround4(
    const float4* __restrict__ a, const float4* __restrict__ b,
    const float4* __restrict__ c, const float4* __restrict__ d,
    float4* __restrict__ A, float4* __restrict__ B,
    float4* __restrict__ C, float4* __restrict__ D)
{
    size_t i = (size_t)blockIdx.x * 256 + threadIdx.x;
    const float4* src = (blockIdx.y == 0) ? a : (blockIdx.y == 1) ? b : (blockIdx.y == 2) ? c : d;
    float4* dst       = (blockIdx.y == 0) ? A : (blockIdx.y == 1) ? B : (blockIdx.y == 2) ? C : D;
    float4 v = src[i];
    v.x = ftf(v.x); v.y = ftf(v.y); v.z = ftf(v.z); v.w = ftf(v.w);
    dst[i] = v;
}

// =====================================================================
// Fused projection GEMM (tf32 MMA + cp.async 2-stage pipeline).
// Inputs pre-rounded. Block 128x128, KC=32, 256 thr (8 warps, 32x64 tiles).
// grid = (1, S/128, 3*B*H). Epilogue stores tf32-rounded fp32.
// =====================================================================
#define ASTR 36
#define BSTR 136
#define ATILE (128 * ASTR)
#define BTILE (32 * BSTR)

__global__ __launch_bounds__(256, 2) void proj_tc(
    const float* __restrict__ Xq, const float* __restrict__ Xk, const float* __restrict__ Xv,
    const float* __restrict__ Wq, const float* __restrict__ Wk, const float* __restrict__ Wv,
    float* __restrict__ Oq, float* __restrict__ Ok, float* __restrict__ Ov,
    float qscale)
{
    extern __shared__ unsigned smp[];
    unsigned* Abuf = smp;                 // 2 * 128*36
    unsigned* Bbuf = smp + 2 * ATILE;     // 2 * 32*136

    int zz = blockIdx.z;
    int which = zz >> 5;
    int bh = zz & 31;
    int b = bh >> 3, h = bh & 7;

    const float* X = (which == 0) ? Xq : (which == 1) ? Xk : Xv;
    const float* W = (which == 0) ? Wq : (which == 1) ? Wk : Wv;
    float* Out     = (which == 0) ? Oq : (which == 1) ? Ok : Ov;
    float scale    = (which == 0) ? qscale : 1.0f;

    const float* A  = X + (size_t)b * SS * DD;
    const float* Bw = W + (size_t)h * DD * EE;
    float* C = Out + (size_t)bh * SS * EE;
    int s0 = blockIdx.y * 128;

    int tid = threadIdx.x;
    int warp = tid >> 5, lane = tid & 31;
    int g = lane >> 2, c = lane & 3;
    int wm = warp >> 1, wn = warp & 1;

    // per-thread cp.async coordinates
    int ar = tid >> 1, ac4 = (tid & 1) * 4;          // A: 2 rows chunk? no: below loop
    (void)ar; (void)ac4;

    float acc[2][8][4];
#pragma unroll
    for (int i = 0; i < 2; i++)
#pragma unroll
        for (int j = 0; j < 8; j++)
#pragma unroll
            for (int t = 0; t < 4; t++) acc[i][j][t] = 0.f;

    // prologue: stage 0
#pragma unroll
    for (int it = 0; it < 4; it++) {
        int idx = tid + it * 256;
        int r = idx >> 3, c4 = (idx & 7) * 4;
        cp16(&Abuf[r * ASTR + c4], A + (size_t)(s0 + r) * DD + c4);
        int r2 = idx >> 5, c42 = (idx & 31) * 4;
        cp16(&Bbuf[r2 * BSTR + c42], Bw + (size_t)r2 * EE + c42);
    }
    CP_COMMIT();

    int s = 0;
    for (int k0 = 0; k0 < DD; k0 += 32) {
        if (k0 + 32 < DD) {
            unsigned* An = Abuf + (s ^ 1) * ATILE;
            unsigned* Bn = Bbuf + (s ^ 1) * BTILE;
#pragma unroll
            for (int it = 0; it < 4; it++) {
                int idx = tid + it * 256;
                int r = idx >> 3, c4 = (idx & 7) * 4;
                cp16(&An[r * ASTR + c4], A + (size_t)(s0 + r) * DD + k0 + 32 + c4);
                int r2 = idx >> 5, c42 = (idx & 31) * 4;
                cp16(&Bn[r2 * BSTR + c42], Bw + (size_t)(k0 + 32 + r2) * EE + c42);
            }
            CP_COMMIT();
            CP_WAIT1();
        } else {
            CP_WAIT0();
        }
        __syncthreads();

        const unsigned* As = Abuf + s * ATILE;
        const unsigned* Bs = Bbuf + s * BTILE;
#pragma unroll
        for (int kk = 0; kk < 32; kk += 8) {
            unsigned a[2][4];
#pragma unroll
            for (int mi = 0; mi < 2; mi++) {
                int base = (wm * 32 + mi * 16 + g) * ASTR + kk + c;
                a[mi][0] = As[base];
                a[mi][1] = As[base + 8 * ASTR];
                a[mi][2] = As[base + 4];
                a[mi][3] = As[base + 8 * ASTR + 4];
            }
            unsigned bf[8][2];
#pragma unroll
            for (int jt = 0; jt < 8; jt++) {
                int base = (kk + c) * BSTR + wn * 64 + jt * 8 + g;
                bf[jt][0] = Bs[base];
                bf[jt][1] = Bs[base + 4 * BSTR];
            }
#pragma unroll
            for (int mi = 0; mi < 2; mi++)
#pragma unroll
                for (int jt = 0; jt < 8; jt++)
                    mma_tf32(acc[mi][jt][0], acc[mi][jt][1], acc[mi][jt][2], acc[mi][jt][3],
                             a[mi][0], a[mi][1], a[mi][2], a[mi][3],
                             bf[jt][0], bf[jt][1]);
        }
        __syncthreads();
        s ^= 1;
    }

    // epilogue: store tf32-rounded (flash consumes via cp.async)
#pragma unroll
    for (int mi = 0; mi < 2; mi++) {
        int r = s0 + wm * 32 + mi * 16 + g;
#pragma unroll
        for (int jt = 0; jt < 8; jt++) {
            int col = wn * 64 + jt * 8 + 2 * c;
            *(float2*)(C + (size_t)r * EE + col) =
                make_float2(ftf(acc[mi][jt][0] * scale), ftf(acc[mi][jt][1] * scale));
            *(float2*)(C + (size_t)(r + 8) * EE + col) =
                make_float2(ftf(acc[mi][jt][2] * scale), ftf(acc[mi][jt][3] * scale));
        }
    }
}

// =====================================================================
// Output GEMM (tf32 MMA + cp.async): Out = Z*Wo + bo  (fp32 output)
// grid = (D/128, B*S/128)
// =====================================================================
__global__ __launch_bounds__(256, 2) void out_tc(
    const float* __restrict__ Z, const float* __restrict__ Wo,
    const float* __restrict__ bo, float* __restrict__ Out)
{
    extern __shared__ unsigned smp[];
    unsigned* Abuf = smp;
    unsigned* Bbuf = smp + 2 * ATILE;

    int row0 = blockIdx.y * 128;
    int col0 = blockIdx.x * 128;

    int tid = threadIdx.x;
    int warp = tid >> 5, lane = tid & 31;
    int g = lane >> 2, c = lane & 3;
    int wm = warp >> 1, wn = warp & 1;

    float acc[2][8][4];
#pragma unroll
    for (int i = 0; i < 2; i++)
#pragma unroll
        for (int j = 0; j < 8; j++)
#pragma unroll
            for (int t = 0; t < 4; t++) acc[i][j][t] = 0.f;

#pragma unroll
    for (int it = 0; it < 4; it++) {
        int idx = tid + it * 256;
        int r = idx >> 3, c4 = (idx & 7) * 4;
        cp16(&Abuf[r * ASTR + c4], Z + (size_t)(row0 + r) * HE + c4);
        int r2 = idx >> 5, c42 = (idx & 31) * 4;
        cp16(&Bbuf[r2 * BSTR + c42], Wo + (size_t)r2 * DD + col0 + c42);
    }
    CP_COMMIT();

    int s = 0;
    for (int k0 = 0; k0 < HE; k0 += 32) {
        if (k0 + 32 < HE) {
            unsigned* An = Abuf + (s ^ 1) * ATILE;
            unsigned* Bn = Bbuf + (s ^ 1) * BTILE;
#pragma unroll
            for (int it = 0; it < 4; it++) {
                int idx = tid + it * 256;
                int r = idx >> 3, c4 = (idx & 7) * 4;
                cp16(&An[r * ASTR + c4], Z + (size_t)(row0 + r) * HE + k0 + 32 + c4);
                int r2 = idx >> 5, c42 = (idx & 31) * 4;
                cp16(&Bn[r2 * BSTR + c42], Wo + (size_t)(k0 + 32 + r2) * DD + col0 + c42);
            }
            CP_COMMIT();
            CP_WAIT1();
        } else {
            CP_WAIT0();
        }
        __syncthreads();

        const unsigned* As = Abuf + s * ATILE;
        const unsigned* Bs = Bbuf + s * BTILE;
#pragma unroll
        for (int kk = 0; kk < 32; kk += 8) {
            unsigned a[2][4];
#pragma unroll
            for (int mi = 0; mi < 2; mi++) {
                int base = (wm * 32 + mi * 16 + g) * ASTR + kk + c;
                a[mi][0] = As[base];
                a[mi][1] = As[base + 8 * ASTR];
                a[mi][2] = As[base + 4];
                a[mi][3] = As[base + 8 * ASTR + 4];
            }
            unsigned bf[8][2];
#pragma unroll
            for (int jt = 0; jt < 8; jt++) {
                int base = (kk + c) * BSTR + wn * 64 + jt * 8 + g;
                bf[jt][0] = Bs[base];
                bf[jt][1] = Bs[base + 4 * BSTR];
            }
#pragma unroll
            for (int mi = 0; mi < 2; mi++)
#pragma unroll
                for (int jt = 0; jt < 8; jt++)
                    mma_tf32(acc[mi][jt][0], acc[mi][jt][1], acc[mi][jt][2], acc[mi][jt][3],
                             a[mi][0], a[mi][1], a[mi][2], a[mi][3],
                             bf[jt][0], bf[jt][1]);
        }
        __syncthreads();
        s ^= 1;
    }

#pragma unroll
    for (int mi = 0; mi < 2; mi++) {
        int r = row0 + wm * 32 + mi * 16 + g;
#pragma unroll
        for (int jt = 0; jt < 8; jt++) {
            int col = col0 + wn * 64 + jt * 8 + 2 * c;
            float b0 = bo[col], b1 = bo[col + 1];
            *(float2*)(Out + (size_t)r * DD + col) =
                make_float2(acc[mi][jt][0] + b0, acc[mi][jt][1] + b1);
            *(float2*)(Out + (size_t)(r + 8) * DD + col) =
                make_float2(acc[mi][jt][2] + b0, acc[mi][jt][3] + b1);
        }
    }
}

// =====================================================================
// Flash attention v4 (tf32 MMA + cp.async K/V pipeline), per (b,h).
// FBM=128 q rows, FBN=64 keys/tile, 512 threads (16 warps).
// QK warp tile 16x32 (8x2 grid), PV warp tile 32x32 (4x4 grid).
// K buffer and V buffer fixed; next tile issued right after its consumer
// phase, landing during the other phase. grid = (S/128, B*H).
// =====================================================================
#define FBM 128
#define FBN 64
#define QSTR 132
#define SP 68
#define NT (SS / FBN)   // 32

extern "C" __global__ __launch_bounds__(512, 1) void flash_tc(
    const float* __restrict__ qh, const float* __restrict__ kh,
    const float* __restrict__ vh, float* __restrict__ z)
{
    extern __shared__ unsigned sm[];
    unsigned* Qs = sm;                         // 128*132
    unsigned* Ks = Qs + FBM * QSTR;            // 64*132
    unsigned* Vs = Ks + FBN * QSTR;            // 64*132
    float*    Sf = (float*)(Vs + FBN * QSTR);  // 128*68 scores fp32 / P tf32
    unsigned* Su = (unsigned*)Sf;
    float* mrow = Sf + FBM * SP;               // 128
    float* lrow = mrow + FBM;
    float* arow = lrow + FBM;

    int bh = blockIdx.y;
    int b = bh >> 3, h = bh & 7;
    int q0 = blockIdx.x * FBM;

    const float* Qg = qh + ((size_t)bh * SS + q0) * EE;
    const float* Kg = kh + (size_t)bh * SS * EE;
    const float* Vg = vh + (size_t)bh * SS * EE;

    int tid = threadIdx.x;
    int warp = tid >> 5, lane = tid & 31;
    int g = lane >> 2, c = lane & 3;
    int w8 = warp >> 1, w2 = warp & 1;   // QK grid 8x2
    int wm = warp >> 2, wn = warp & 3;   // PV grid 4x4

    // ---- issue K(0), V(0) via cp.async (2 groups) ----
#pragma unroll
    for (int i = 0; i < 4; i++) {
        int flat = tid + i * 512;
        int r = flat >> 5, c4 = (flat & 31) * 4;
        cp16(&Ks[r * QSTR + c4], Kg + (size_t)r * EE + c4);
    }
    CP_COMMIT();
#pragma unroll
    for (int i = 0; i < 4; i++) {
        int flat = tid + i * 512;
        int r = flat >> 5, c4 = (flat & 31) * 4;
        cp16(&Vs[r * QSTR + c4], Vg + (size_t)r * EE + c4);
    }
    CP_COMMIT();

    // ---- stage Q (pre-rounded, plain copy) ----
#pragma unroll
    for (int it = 0; it < 8; it++) {
        int idx = tid + it * 512;
        int r = idx >> 5, c4 = (idx & 31) * 4;
        *(uint4*)(&Qs[r * QSTR + c4]) = *(const uint4*)(Qg + (size_t)r * EE + c4);
    }
    if (tid < FBM) { mrow[tid] = NEG_BIG; lrow[tid] = 0.f; }

    float o[2][4][4];
#pragma unroll
    for (int i = 0; i < 2; i++)
#pragma unroll
        for (int j = 0; j < 4; j++)
#pragma unroll
            for (int t = 0; t < 4; t++) o[i][j][t] = 0.f;

    int srow = tid >> 2;   // softmax row
    int part = tid & 3;    // column quarter (stride-4 interleave)

    for (int kt = 0; kt < NT; kt++) {
        CP_WAIT1();            // K(kt) landed (V(kt) may be pending)
        __syncthreads();

        // ================= QK^T: S[128x64], warp tile 16x32 =================
        float sc[4][4];
#pragma unroll
        for (int j = 0; j < 4; j++)
#pragma unroll
            for (int t = 0; t < 4; t++) sc[j][t] = 0.f;

#pragma unroll
        for (int kk = 0; kk < EE; kk += 8) {
            unsigned a[4];
            int abase = (w8 * 16 + g) * QSTR + kk + c;
            a[0] = Qs[abase];
            a[1] = Qs[abase + 8 * QSTR];
            a[2] = Qs[abase + 4];
            a[3] = Qs[abase + 8 * QSTR + 4];
            unsigned bf[4][2];
#pragma unroll
            for (int jt = 0; jt < 4; jt++) {
                int bb = (w2 * 32 + jt * 8 + g) * QSTR + kk + c;
                bf[jt][0] = Ks[bb];
                bf[jt][1] = Ks[bb + 4];
            }
#pragma unroll
            for (int jt = 0; jt < 4; jt++)
                mma_tf32(sc[jt][0], sc[jt][1], sc[jt][2], sc[jt][3],
                         a[0], a[1], a[2], a[3], bf[jt][0], bf[jt][1]);
        }
        {
            int r = w8 * 16 + g;
#pragma unroll
            for (int jt = 0; jt < 4; jt++) {
                int col = w2 * 32 + jt * 8 + 2 * c;
                *(float2*)(Sf + r * SP + col)       = make_float2(sc[jt][0], sc[jt][1]);
                *(float2*)(Sf + (r + 8) * SP + col) = make_float2(sc[jt][2], sc[jt][3]);
            }
        }
        __syncthreads();   // S visible; all warps done reading Ks

        // issue K(kt+1) into Ks (lands during softmax+PV)
        if (kt + 1 < NT) {
            const float* src = Kg + (size_t)(kt + 1) * FBN * EE;
#pragma unroll
            for (int i = 0; i < 4; i++) {
                int flat = tid + i * 512;
                int r = flat >> 5, c4 = (flat & 31) * 4;
                cp16(&Ks[r * QSTR + c4], src + (size_t)r * EE + c4);
            }
            CP_COMMIT();
        }

        // ---- online softmax (4 lanes/row, 16 cols each) ----
        {
            float* row = Sf + srow * SP;
            float vmax = NEG_BIG;
#pragma unroll
            for (int j = 0; j < 16; j++)
                vmax = fmaxf(vmax, row[part + 4 * j]);
            vmax = fmaxf(vmax, __shfl_xor_sync(0xffffffffu, vmax, 1));
            vmax = fmaxf(vmax, __shfl_xor_sync(0xffffffffu, vmax, 2));
            float m_old = mrow[srow];
            float m_new = fmaxf(m_old, vmax);
            float sum = 0.f;
            unsigned* rowu = Su + srow * SP;
#pragma unroll
            for (int j = 0; j < 16; j++) {
                float p = __expf(row[part + 4 * j] - m_new);
                sum += p;
                rowu[part + 4 * j] = f2tf(p);
            }
            sum += __shfl_xor_sync(0xffffffffu, sum, 1);
            sum += __shfl_xor_sync(0xffffffffu, sum, 2);
            if (part == 0) {
                float al = expf(m_old - m_new);
                arow[srow] = al;
                mrow[srow] = m_new;
                lrow[srow] = lrow[srow] * al + sum;
            }
        }

        // wait V(kt): pending = {V(kt), K(kt+1)} (or just {V(kt)} on last iter)
        if (kt + 1 < NT) { CP_WAIT1(); } else { CP_WAIT0(); }
        __syncthreads();   // P + stats + V visible

        // ---- rescale O; PV: O[128x128] += P[128x64]*V[64x128], tile 32x32 ----
        {
            float a0 = arow[wm * 32 + g];
            float a1 = arow[wm * 32 + 8 + g];
            float a2 = arow[wm * 32 + 16 + g];
            float a3 = arow[wm * 32 + 24 + g];
#pragma unroll
            for (int jt = 0; jt < 4; jt++) {
                o[0][jt][0] *= a0; o[0][jt][1] *= a0;
                o[0][jt][2] *= a1; o[0][jt][3] *= a1;
                o[1][jt][0] *= a2; o[1][jt][1] *= a2;
                o[1][jt][2] *= a3; o[1][jt][3] *= a3;
            }
        }
#pragma unroll
        for (int kk = 0; kk < FBN; kk += 8) {
            unsigned a[2][4];
#pragma unroll
            for (int mi = 0; mi < 2; mi++) {
                int base = (wm * 32 + mi * 16 + g) * SP + kk + c;
                a[mi][0] = Su[base];
                a[mi][1] = Su[base + 8 * SP];
                a[mi][2] = Su[base + 4];
                a[mi][3] = Su[base + 8 * SP + 4];
            }
            unsigned bf[4][2];
#pragma unroll
            for (int jt = 0; jt < 4; jt++) {
                int col = wn * 32 + jt * 8 + g;
                bf[jt][0] = Vs[(kk + c) * QSTR + col];
                bf[jt][1] = Vs[(kk + c + 4) * QSTR + col];
            }
#pragma unroll
            for (int mi = 0; mi < 2; mi++)
#pragma unroll
                for (int jt = 0; jt < 4; jt++)
                    mma_tf32(o[mi][jt][0], o[mi][jt][1], o[mi][jt][2], o[mi][jt][3],
                             a[mi][0], a[mi][1], a[mi][2], a[mi][3],
                             bf[jt][0], bf[jt][1]);
        }
        __syncthreads();   // all warps done reading Vs (and Su)

        // issue V(kt+1) into Vs (lands during next QK + softmax)
        if (kt + 1 < NT) {
            const float* src = Vg + (size_t)(kt + 1) * FBN * EE;
#pragma unroll
            for (int i = 0; i < 4; i++) {
                int flat = tid + i * 512;
                int r = flat >> 5, c4 = (flat & 31) * 4;
                cp16(&Vs[r * QSTR + c4], src + (size_t)r * EE + c4);
            }
            CP_COMMIT();
        }
    }

    // ---- finalize: divide by l, store tf32-rounded (out_tc cp.asyncs z) ----
    {
        float li0 = 1.f / lrow[wm * 32 + g];
        float li1 = 1.f / lrow[wm * 32 + 8 + g];
        float li2 = 1.f / lrow[wm * 32 + 16 + g];
        float li3 = 1.f / lrow[wm * 32 + 24 + g];
#pragma unroll
        for (int mi = 0; mi < 2; mi++) {
            int r = wm * 32 + mi * 16 + g;
            float lia = (mi == 0) ? li0 : li2;
            float lib = (mi == 0) ? li1 : li3;
            float* z0 = z + ((size_t)(b * SS + q0 + r)) * HE + h * EE;
            float* z1 = z + ((size_t)(b * SS + q0 + r + 8)) * HE + h * EE;
#pragma unroll
            for (int jt = 0; jt < 4; jt++) {
                int col = wn * 32 + jt * 8 + 2 * c;
                *(float2*)(z0 + col) = make_float2(ftf(o[mi][jt][0] * lia), ftf(o[mi][jt][1] * lia));
                *(float2*)(z1 + col) = make_float2(ftf(o[mi][jt][2] * lib), ftf(o[mi][jt][3] * lib));
            }
        }
    }
}

// =====================================================================
// launch
// =====================================================================
extern "C" void kernel_launch(void* const* d_in, const int* in_sizes, int n_in,
                              void* d_out, int out_size)
{
    const float* q  = (const float*)d_in[0];
    const float* k  = (const float*)d_in[1];
    const float* v  = (const float*)d_in[2];
    const float* Wq = (const float*)d_in[3];
    const float* Wk = (const float*)d_in[4];
    const float* Wv = (const float*)d_in[5];
    const float* Wo = (const float*)d_in[6];
    const float* bo = (const float*)d_in[7];
    float* out = (float*)d_out;

    float* qh; cudaGetSymbolAddress((void**)&qh, g_qh);
    float* kh; cudaGetSymbolAddress((void**)&kh, g_kh);
    float* vh; cudaGetSymbolAddress((void**)&vh, g_vh);
    float* z;  cudaGetSymbolAddress((void**)&z,  g_z);
    float* qr; cudaGetSymbolAddress((void**)&qr, g_qr);
    float* kr; cudaGetSymbolAddress((void**)&kr, g_kr);
    float* vr; cudaGetSymbolAddress((void**)&vr, g_vr);
    float* wq; cudaGetSymbolAddress((void**)&wq, g_wq);
    float* wk; cudaGetSymbolAddress((void**)&wk, g_wk);
    float* wv; cudaGetSymbolAddress((void**)&wv, g_wv);
    float* wo; cudaGetSymbolAddress((void**)&wo, g_wo);

    const int gemm_smem = 2 * (ATILE + BTILE) * (int)sizeof(unsigned);
    cudaFuncSetAttribute(proj_tc, cudaFuncAttributeMaxDynamicSharedMemorySize, gemm_smem);
    cudaFuncSetAttribute(out_tc,  cudaFuncAttributeMaxDynamicSharedMemorySize, gemm_smem);
    const int flash_smem =
        (FBM * QSTR + 2 * FBN * QSTR + FBM * SP + 3 * FBM) * (int)sizeof(unsigned);
    cudaFuncSetAttribute(flash_tc, cudaFuncAttributeMaxDynamicSharedMemorySize, flash_smem);

    float qscale = 1.0f / sqrtf((float)EE);

    // pre-round inputs and weights (tf32 RNA) into scratch
    {
        dim3 g3((BB * SS * DD) / 4 / 256, 3);
        preround3<<<g3, 256>>>((const float4*)q, (const float4*)k, (const float4*)v,
                               (float4*)qr, (float4*)kr, (float4*)vr);
        dim3 g4((HH * DD * EE) / 4 / 256, 4);
        preround4<<<g4, 256>>>((const float4*)Wq, (const float4*)Wk,
                               (const float4*)Wv, (const float4*)Wo,
                               (float4*)wq, (float4*)wk, (float4*)wv, (float4*)wo);
    }

    dim3 pgrid(1, SS / 128, 3 * BB * HH);
    proj_tc<<<pgrid, 256, gemm_smem>>>(qr, kr, vr, wq, wk, wv, qh, kh, vh, qscale);

    dim3 fgrid(SS / FBM, BB * HH);
    flash_tc<<<fgrid, 512, flash_smem>>>(qh, kh, vh, z);

    dim3 ogrid(DD / 128, (BB * SS) / 128);
    out_tc<<<ogrid, 256, gemm_smem>>>(z, wo, bo, out);
}